// round 2
// baseline (speedup 1.0000x reference)
#include <cuda_runtime.h>
#include <math.h>

// Problem constants
#define Nn 128
#define Cc 64
#define Tt 128
#define Vv 25
#define Rr 8
#define Hh 12

// Scratch (device globals; no allocation allowed)
__device__ float g_xm[Nn * Cc * Vv];          // mean over T      (0.8 MB)
__device__ float g_Aeff[Nn * Cc * Vv * Vv];   // effective adjacency incl. SE scale (20.5 MB)

// ---------- f32x2 helpers (Blackwell packed fp32) ----------
__device__ __forceinline__ unsigned long long pack2(float lo, float hi) {
    unsigned long long r;
    asm("mov.b64 %0, {%1, %2};" : "=l"(r) : "f"(lo), "f"(hi));
    return r;
}
__device__ __forceinline__ void unpack2(unsigned long long x, float& lo, float& hi) {
    asm("mov.b64 {%0, %1}, %2;" : "=f"(lo), "=f"(hi) : "l"(x));
}
__device__ __forceinline__ unsigned long long fma2(unsigned long long a,
                                                   unsigned long long b,
                                                   unsigned long long c) {
    unsigned long long d;
    asm("fma.rn.f32x2 %0, %1, %2, %3;" : "=l"(d) : "l"(a), "l"(b), "l"(c));
    return d;
}
__device__ __forceinline__ unsigned long long add2(unsigned long long a,
                                                   unsigned long long b) {
    unsigned long long d;
    asm("add.rn.f32x2 %0, %1, %2;" : "=l"(d) : "l"(a), "l"(b));
    return d;
}

// ================= Kernel 1: xm[n,c,v] = mean_t x[n,c,t,v] =================
// One block per (n,c). blockDim = (25, 8). Each thread owns a fixed v,
// sums T/8 frames -> no atomics, no dynamic-indexed accumulators.
__global__ void k1_meanT(const float* __restrict__ x) {
    const int b = blockIdx.x;                 // n*C + c
    const float* xp = x + (size_t)b * (Tt * Vv);
    const int v = threadIdx.x;                // 0..24
    const int ty = threadIdx.y;               // 0..7

    float s = 0.f;
    #pragma unroll
    for (int k = 0; k < Tt / 8; k++) {
        s += xp[(ty + 8 * k) * Vv + v];
    }
    __shared__ float red[8][Vv];
    red[ty][v] = s;
    __syncthreads();
    if (ty == 0) {
        float tot = 0.f;
        #pragma unroll
        for (int j = 0; j < 8; j++) tot += red[j][v];
        g_xm[b * Vv + v] = tot * (1.0f / Tt);
    }
}

// ============ Kernel 2: per-n relation matrix + SE attention ============
// One block per n (128 blocks, 256 threads). Produces
//   Aeff[n,c,u,v] = (sum_r w4[c,r]*tanh(x1[r,u]-x2[r,v]) + b4[c] + A[u,v]) * a[n,v]
__global__ void k2_adj(const float* __restrict__ A,
                       const float* __restrict__ w1, const float* __restrict__ b1,
                       const float* __restrict__ w2, const float* __restrict__ b2,
                       const float* __restrict__ w4, const float* __restrict__ b4,
                       const float* __restrict__ sw1, const float* __restrict__ sb1,
                       const float* __restrict__ sw2, const float* __restrict__ sb2) {
    const int n = blockIdx.x;
    const int tid = threadIdx.x;
    const int NT = 256;

    __shared__ float xm_sh[Cc * Vv];      // 1600
    __shared__ float w1s[Rr * Cc], w2s[Rr * Cc], w4s[Cc * Rr];
    __shared__ float sw1s[Hh * Vv], sw2s[Vv * Hh];
    __shared__ float A_s[Vv * Vv];
    __shared__ float b1s[Rr], b2s[Rr], b4s[Cc], sb1s[Hh], sb2s[Vv];
    __shared__ float s_sh[Vv], h_sh[Hh], a_sh[Vv];
    __shared__ float x1_sh[Rr * Vv], x2_sh[Rr * Vv];
    __shared__ float rel_sh[Rr * Vv * Vv]; // 5000

    for (int i = tid; i < Cc * Vv; i += NT) xm_sh[i] = g_xm[n * Cc * Vv + i];
    for (int i = tid; i < Rr * Cc; i += NT) { w1s[i] = w1[i]; w2s[i] = w2[i]; w4s[i] = w4[i]; }
    for (int i = tid; i < Hh * Vv; i += NT) { sw1s[i] = sw1[i]; sw2s[i] = sw2[i]; }
    for (int i = tid; i < Vv * Vv; i += NT) A_s[i] = A[i];
    if (tid < Rr) { b1s[tid] = b1[tid]; b2s[tid] = b2[tid]; }
    if (tid < Cc) b4s[tid] = b4[tid];
    if (tid < Hh) sb1s[tid] = sb1[tid];
    if (tid < Vv) sb2s[tid] = sb2[tid];
    __syncthreads();

    // s[v] = mean over c of xm
    if (tid < Vv) {
        float acc = 0.f;
        for (int c = 0; c < Cc; c++) acc += xm_sh[c * Vv + tid];
        s_sh[tid] = acc * (1.0f / Cc);
    }
    __syncthreads();
    if (tid < Hh) {
        float acc = sb1s[tid];
        for (int v = 0; v < Vv; v++) acc += sw1s[tid * Vv + v] * s_sh[v];
        h_sh[tid] = fmaxf(acc, 0.f);
    }
    __syncthreads();
    if (tid < Vv) {
        float acc = sb2s[tid];
        for (int j = 0; j < Hh; j++) acc += sw2s[tid * Hh + j] * h_sh[j];
        a_sh[tid] = 1.0f / (1.0f + expf(-acc));
    }

    // x1[r,v], x2[r,v]
    for (int i = tid; i < Rr * Vv; i += NT) {
        int r = i / Vv, v = i % Vv;
        float acc1 = b1s[r], acc2 = b2s[r];
        for (int c = 0; c < Cc; c++) {
            float xm = xm_sh[c * Vv + v];
            acc1 += w1s[r * Cc + c] * xm;
            acc2 += w2s[r * Cc + c] * xm;
        }
        x1_sh[i] = acc1;
        x2_sh[i] = acc2;
    }
    __syncthreads();

    // rel[r,u,v] = tanh(x1[r,u] - x2[r,v])
    for (int i = tid; i < Rr * Vv * Vv; i += NT) {
        int r = i / (Vv * Vv), rem = i % (Vv * Vv);
        int u = rem / Vv, v = rem % Vv;
        rel_sh[i] = tanhf(x1_sh[r * Vv + u] - x2_sh[r * Vv + v]);
    }
    __syncthreads();

    // Aeff[c,u,v] = (sum_r w4[c,r]*rel + b4[c] + A[u,v]) * a[v]
    float* outp = g_Aeff + (size_t)n * Cc * Vv * Vv;
    for (int i = tid; i < Cc * Vv * Vv; i += NT) {
        int c = i / (Vv * Vv), rem = i % (Vv * Vv);
        int v = rem % Vv;
        float acc = b4s[c] + A_s[rem];
        #pragma unroll
        for (int r = 0; r < Rr; r++) acc += w4s[c * Rr + r] * rel_sh[r * Vv * Vv + rem];
        outp[i] = acc * a_sh[v];
    }
}

// ============ Kernel 3: out[t,u] = sum_v Aeff[u,v] * x[t,v] per (n,c) ============
// One block per (n,c), 64 threads; each thread computes rows t and t+64 as a
// packed f32x2 pair. Aeff is duplicated into (a,a) pairs in shared so the
// inner loop is LDS.64 + FFMA2 (2 issues per 2 lane-MACs).
__global__ void __launch_bounds__(64) k3_gemm(const float* __restrict__ x,
                                              float* __restrict__ out) {
    __shared__ float xs[Tt * Vv];       // 3200 floats; reused as out staging
    __shared__ float2 a2sh[Vv * Vv];    // 625 duplicated pairs

    const int b = blockIdx.x;           // n*C + c
    const int tid = threadIdx.x;

    // Load x tile (float4, 16B aligned: 12800B per block)
    const float4* xp4 = reinterpret_cast<const float4*>(x + (size_t)b * (Tt * Vv));
    float4* xs4 = reinterpret_cast<float4*>(xs);
    #pragma unroll
    for (int i = tid; i < (Tt * Vv) / 4; i += 64) xs4[i] = xp4[i];

    // Load Aeff, duplicate into pairs
    const float* ae = g_Aeff + (size_t)b * (Vv * Vv);
    for (int i = tid; i < Vv * Vv; i += 64) {
        float w = ae[i];
        a2sh[i] = make_float2(w, w);
    }
    __syncthreads();

    // Pull this thread's two x rows into registers (bank-conflict-free: 25 ⊥ 32)
    const int t0 = tid, t1 = tid + 64;
    unsigned long long xv[Vv];
    #pragma unroll
    for (int v = 0; v < Vv; v++)
        xv[v] = pack2(xs[t0 * Vv + v], xs[t1 * Vv + v]);
    __syncthreads();   // xs now free for output staging

    const unsigned long long* a2u = reinterpret_cast<const unsigned long long*>(a2sh);
    #pragma unroll 1
    for (int u = 0; u < Vv; u++) {
        unsigned long long acc0 = 0ull, acc1 = 0ull;  // (0.f,0.f) bit pattern
        const unsigned long long* arow = a2u + u * Vv;
        #pragma unroll
        for (int v = 0; v < Vv - 1; v += 2) {
            acc0 = fma2(xv[v],     arow[v],     acc0);
            acc1 = fma2(xv[v + 1], arow[v + 1], acc1);
        }
        acc0 = fma2(xv[Vv - 1], arow[Vv - 1], acc0);
        acc0 = add2(acc0, acc1);
        float lo, hi;
        unpack2(acc0, lo, hi);
        xs[t0 * Vv + u] = lo;
        xs[t1 * Vv + u] = hi;
    }
    __syncthreads();

    float4* op4 = reinterpret_cast<float4*>(out + (size_t)b * (Tt * Vv));
    #pragma unroll
    for (int i = tid; i < (Tt * Vv) / 4; i += 64) op4[i] = xs4[i];
}

extern "C" void kernel_launch(void* const* d_in, const int* in_sizes, int n_in,
                              void* d_out, int out_size) {
    const float* x   = (const float*)d_in[0];
    const float* A   = (const float*)d_in[1];
    const float* w1  = (const float*)d_in[2];
    const float* b1  = (const float*)d_in[3];
    const float* w2  = (const float*)d_in[4];
    const float* b2  = (const float*)d_in[5];
    const float* w4  = (const float*)d_in[6];
    const float* b4  = (const float*)d_in[7];
    const float* sw1 = (const float*)d_in[8];
    const float* sb1 = (const float*)d_in[9];
    const float* sw2 = (const float*)d_in[10];
    const float* sb2 = (const float*)d_in[11];
    float* out = (float*)d_out;

    k1_meanT<<<Nn * Cc, dim3(Vv, 8)>>>(x);
    k2_adj<<<Nn, 256>>>(A, w1, b1, w2, b2, w4, b4, sw1, sb1, sw2, sb2);
    k3_gemm<<<Nn * Cc, 64>>>(x, out);
}

// round 3
// speedup vs baseline: 1.0043x; 1.0043x over previous
#include <cuda_runtime.h>
#include <math.h>

// Problem constants
#define Nn 128
#define Cc 64
#define Tt 128
#define Vv 25
#define Rr 8
#define Hh 12

// Scratch (device globals; no allocation allowed)
__device__ float g_xm[Nn * Cc * Vv];          // mean over T      (0.8 MB)
__device__ float g_Aeff[Nn * Cc * Vv * Vv];   // effective adjacency incl. SE scale (20.5 MB)

// ---------- f32x2 helpers (Blackwell packed fp32) ----------
__device__ __forceinline__ unsigned long long pack2(float lo, float hi) {
    unsigned long long r;
    asm("mov.b64 %0, {%1, %2};" : "=l"(r) : "f"(lo), "f"(hi));
    return r;
}
__device__ __forceinline__ void unpack2(unsigned long long x, float& lo, float& hi) {
    asm("mov.b64 {%0, %1}, %2;" : "=f"(lo), "=f"(hi) : "l"(x));
}
__device__ __forceinline__ unsigned long long fma2(unsigned long long a,
                                                   unsigned long long b,
                                                   unsigned long long c) {
    unsigned long long d;
    asm("fma.rn.f32x2 %0, %1, %2, %3;" : "=l"(d) : "l"(a), "l"(b), "l"(c));
    return d;
}
__device__ __forceinline__ unsigned long long add2(unsigned long long a,
                                                   unsigned long long b) {
    unsigned long long d;
    asm("add.rn.f32x2 %0, %1, %2;" : "=l"(d) : "l"(a), "l"(b));
    return d;
}

// ================= Kernel 1: xm[n,c,v] = mean_t x[n,c,t,v] =================
// One block per (n,c), 200 threads. Thread j loads float4s at q = j, j+200,
// j+400, j+600 (stride 800 floats == 0 mod 25, so each float4 component keeps
// a FIXED v across iterations). Register accumulation, then a conflict-free
// stride-25 shared reduction (red[v + 25p], 25 coprime 32).
__global__ void __launch_bounds__(200) k1_meanT(const float* __restrict__ x) {
    const int b = blockIdx.x;                 // n*C + c
    const int j = threadIdx.x;                // 0..199
    const float4* xp4 = reinterpret_cast<const float4*>(x + (size_t)b * (Tt * Vv));

    float4 a0 = xp4[j];
    float4 a1 = xp4[j + 200];
    float4 a2 = xp4[j + 400];
    float4 a3 = xp4[j + 600];

    __shared__ float red[800];
    red[4 * j + 0] = a0.x + a1.x + a2.x + a3.x;
    red[4 * j + 1] = a0.y + a1.y + a2.y + a3.y;
    red[4 * j + 2] = a0.z + a1.z + a2.z + a3.z;
    red[4 * j + 3] = a0.w + a1.w + a2.w + a3.w;
    __syncthreads();

    if (j < Vv) {
        float tot = 0.f;
        #pragma unroll
        for (int p = 0; p < 32; p++) tot += red[j + Vv * p];
        g_xm[b * Vv + j] = tot * (1.0f / Tt);
    }
}

// ============ Kernel 2: per-n relation matrix + SE attention ============
// Grid (128, 4): each block recomputes the tiny SE / x1 / x2 / rel stage
// (cheap) and writes 16 of the 64 output channels of
//   Aeff[n,c,u,v] = (sum_r w4[c,r]*tanh(x1[r,u]-x2[r,v]) + b4[c] + A[u,v]) * a[n,v]
__global__ void k2_adj(const float* __restrict__ A,
                       const float* __restrict__ w1, const float* __restrict__ b1,
                       const float* __restrict__ w2, const float* __restrict__ b2,
                       const float* __restrict__ w4, const float* __restrict__ b4,
                       const float* __restrict__ sw1, const float* __restrict__ sb1,
                       const float* __restrict__ sw2, const float* __restrict__ sb2) {
    const int n = blockIdx.x;
    const int cblk = blockIdx.y;              // 0..3 -> channels [cblk*16, cblk*16+16)
    const int tid = threadIdx.x;
    const int NT = 256;

    __shared__ float xm_sh[Cc * Vv];      // 1600
    __shared__ float w1s[Rr * Cc], w2s[Rr * Cc], w4s[Cc * Rr];
    __shared__ float sw1s[Hh * Vv], sw2s[Vv * Hh];
    __shared__ float A_s[Vv * Vv];
    __shared__ float b1s[Rr], b2s[Rr], b4s[Cc], sb1s[Hh], sb2s[Vv];
    __shared__ float s_sh[Vv], h_sh[Hh], a_sh[Vv];
    __shared__ float x1_sh[Rr * Vv], x2_sh[Rr * Vv];
    __shared__ float rel_sh[Rr * Vv * Vv]; // 5000

    for (int i = tid; i < Cc * Vv; i += NT) xm_sh[i] = g_xm[n * Cc * Vv + i];
    for (int i = tid; i < Rr * Cc; i += NT) { w1s[i] = w1[i]; w2s[i] = w2[i]; w4s[i] = w4[i]; }
    for (int i = tid; i < Hh * Vv; i += NT) { sw1s[i] = sw1[i]; sw2s[i] = sw2[i]; }
    for (int i = tid; i < Vv * Vv; i += NT) A_s[i] = A[i];
    if (tid < Rr) { b1s[tid] = b1[tid]; b2s[tid] = b2[tid]; }
    if (tid < Cc) b4s[tid] = b4[tid];
    if (tid < Hh) sb1s[tid] = sb1[tid];
    if (tid < Vv) sb2s[tid] = sb2[tid];
    __syncthreads();

    // s[v] = mean over c of xm
    if (tid < Vv) {
        float acc = 0.f;
        for (int c = 0; c < Cc; c++) acc += xm_sh[c * Vv + tid];
        s_sh[tid] = acc * (1.0f / Cc);
    }
    __syncthreads();
    if (tid < Hh) {
        float acc = sb1s[tid];
        for (int v = 0; v < Vv; v++) acc += sw1s[tid * Vv + v] * s_sh[v];
        h_sh[tid] = fmaxf(acc, 0.f);
    }
    __syncthreads();
    if (tid < Vv) {
        float acc = sb2s[tid];
        for (int j = 0; j < Hh; j++) acc += sw2s[tid * Hh + j] * h_sh[j];
        a_sh[tid] = 1.0f / (1.0f + expf(-acc));
    }

    // x1[r,v], x2[r,v]
    for (int i = tid; i < Rr * Vv; i += NT) {
        int r = i / Vv, v = i % Vv;
        float acc1 = b1s[r], acc2 = b2s[r];
        for (int c = 0; c < Cc; c++) {
            float xm = xm_sh[c * Vv + v];
            acc1 += w1s[r * Cc + c] * xm;
            acc2 += w2s[r * Cc + c] * xm;
        }
        x1_sh[i] = acc1;
        x2_sh[i] = acc2;
    }
    __syncthreads();

    // rel[r,u,v] = tanh(x1[r,u] - x2[r,v])
    for (int i = tid; i < Rr * Vv * Vv; i += NT) {
        int r = i / (Vv * Vv), rem = i % (Vv * Vv);
        int u = rem / Vv, v = rem % Vv;
        rel_sh[i] = tanhf(x1_sh[r * Vv + u] - x2_sh[r * Vv + v]);
    }
    __syncthreads();

    // Aeff[c,u,v] for c in this block's 16-channel slice
    const int c0 = cblk * 16;
    float* outp = g_Aeff + ((size_t)n * Cc + c0) * (Vv * Vv);
    for (int i = tid; i < 16 * Vv * Vv; i += NT) {
        int c = c0 + i / (Vv * Vv), rem = i % (Vv * Vv);
        int v = rem % Vv;
        float acc = b4s[c] + A_s[rem];
        #pragma unroll
        for (int r = 0; r < Rr; r++) acc += w4s[c * Rr + r] * rel_sh[r * Vv * Vv + rem];
        outp[i] = acc * a_sh[v];
    }
}

// ============ Kernel 3: out[t,u] = sum_v Aeff[u,v] * x[t,v] per (n,c) ============
// One block per (n,c), 64 threads; each thread computes rows t and t+64 as a
// packed f32x2 pair. Aeff is duplicated into (a,a) pairs in shared, rows
// padded to 26 pairs (208 B, 16B-aligned) so weights load as LDS.128
// broadcast (2 pairs per load): 13 LDS + 13 FFMA2 per u-row.
__global__ void __launch_bounds__(64) k3_gemm(const float* __restrict__ x,
                                              float* __restrict__ out) {
    __shared__ float xs[Tt * Vv];                         // 12.8 KB; reused as out staging
    __shared__ __align__(16) float2 a2sh[Vv * 26];        // padded rows

    const int b = blockIdx.x;           // n*C + c
    const int tid = threadIdx.x;

    // Load x tile (float4, 16B aligned: 12800B per block)
    const float4* xp4 = reinterpret_cast<const float4*>(x + (size_t)b * (Tt * Vv));
    float4* xs4 = reinterpret_cast<float4*>(xs);
    #pragma unroll
    for (int i = tid; i < (Tt * Vv) / 4; i += 64) xs4[i] = xp4[i];

    // Load Aeff, duplicate into padded pair rows
    const float* ae = g_Aeff + (size_t)b * (Vv * Vv);
    for (int i = tid; i < Vv * Vv; i += 64) {
        int u = i / Vv, v = i % Vv;
        float w = ae[i];
        a2sh[u * 26 + v] = make_float2(w, w);
    }
    __syncthreads();

    // Pull this thread's two x rows into registers (stride 25 ⊥ 32: no conflicts)
    const int t0 = tid, t1 = tid + 64;
    unsigned long long xv[Vv];
    #pragma unroll
    for (int v = 0; v < Vv; v++)
        xv[v] = pack2(xs[t0 * Vv + v], xs[t1 * Vv + v]);
    __syncthreads();   // xs now free for output staging

    for (int u = 0; u < Vv; u++) {
        const ulonglong2* arow2 = reinterpret_cast<const ulonglong2*>(a2sh + u * 26);
        unsigned long long acc0 = 0ull, acc1 = 0ull;
        #pragma unroll
        for (int p = 0; p < 12; p++) {
            ulonglong2 w = arow2[p];          // LDS.128, warp-uniform broadcast
            acc0 = fma2(xv[2 * p],     w.x, acc0);
            acc1 = fma2(xv[2 * p + 1], w.y, acc1);
        }
        {   // tail v = 24
            unsigned long long wt =
                *reinterpret_cast<const unsigned long long*>(a2sh + u * 26 + 24);
            acc0 = fma2(xv[24], wt, acc0);
        }
        acc0 = add2(acc0, acc1);
        float lo, hi;
        unpack2(acc0, lo, hi);
        xs[t0 * Vv + u] = lo;
        xs[t1 * Vv + u] = hi;
    }
    __syncthreads();

    float4* op4 = reinterpret_cast<float4*>(out + (size_t)b * (Tt * Vv));
    #pragma unroll
    for (int i = tid; i < (Tt * Vv) / 4; i += 64) op4[i] = xs4[i];
}

extern "C" void kernel_launch(void* const* d_in, const int* in_sizes, int n_in,
                              void* d_out, int out_size) {
    const float* x   = (const float*)d_in[0];
    const float* A   = (const float*)d_in[1];
    const float* w1  = (const float*)d_in[2];
    const float* b1  = (const float*)d_in[3];
    const float* w2  = (const float*)d_in[4];
    const float* b2  = (const float*)d_in[5];
    const float* w4  = (const float*)d_in[6];
    const float* b4  = (const float*)d_in[7];
    const float* sw1 = (const float*)d_in[8];
    const float* sb1 = (const float*)d_in[9];
    const float* sw2 = (const float*)d_in[10];
    const float* sb2 = (const float*)d_in[11];
    float* out = (float*)d_out;

    k1_meanT<<<Nn * Cc, 200>>>(x);
    k2_adj<<<dim3(Nn, 4), 256>>>(A, w1, b1, w2, b2, w4, b4, sw1, sb1, sw2, sb2);
    k3_gemm<<<Nn * Cc, 64>>>(x, out);
}

// round 4
// speedup vs baseline: 1.0749x; 1.0703x over previous
#include <cuda_runtime.h>
#include <math.h>

// Problem constants
#define Nn 128
#define Cc 64
#define Tt 128
#define Vv 25
#define Rr 8
#define Hh 12

// Scratch (device globals; no allocation allowed)
__device__ float g_xm[Nn * Cc * Vv];          // mean over T      (0.8 MB)
__device__ float g_Aeff[Nn * Cc * Vv * Vv];   // effective adjacency incl. SE scale (20.5 MB)

// ================= Kernel 1: xm[n,c,v] = mean_t x[n,c,t,v] =================
// One block per (n,c), 200 threads. Thread j loads float4s at q = j, j+200,
// j+400, j+600 (stride 800 floats == 0 mod 25, so each float4 component keeps
// a FIXED v across iterations). Register accumulation, then a conflict-free
// stride-25 shared reduction.
__global__ void __launch_bounds__(200) k1_meanT(const float* __restrict__ x) {
    const int b = blockIdx.x;                 // n*C + c
    const int j = threadIdx.x;                // 0..199
    const float4* xp4 = reinterpret_cast<const float4*>(x + (size_t)b * (Tt * Vv));

    float4 a0 = xp4[j];
    float4 a1 = xp4[j + 200];
    float4 a2 = xp4[j + 400];
    float4 a3 = xp4[j + 600];

    __shared__ float red[800];
    red[4 * j + 0] = a0.x + a1.x + a2.x + a3.x;
    red[4 * j + 1] = a0.y + a1.y + a2.y + a3.y;
    red[4 * j + 2] = a0.z + a1.z + a2.z + a3.z;
    red[4 * j + 3] = a0.w + a1.w + a2.w + a3.w;
    __syncthreads();

    if (j < Vv) {
        float tot = 0.f;
        #pragma unroll
        for (int p = 0; p < 32; p++) tot += red[j + Vv * p];
        g_xm[b * Vv + j] = tot * (1.0f / Tt);
    }
}

// ============ Kernel 2: per-n relation matrix + SE attention ============
// Grid (128, 4): each block recomputes the tiny SE / x1 / x2 / rel stage
// (cheap) and writes 16 of the 64 output channels of
//   Aeff[n,c,u,v] = (sum_r w4[c,r]*tanh(x1[r,u]-x2[r,v]) + b4[c] + A[u,v]) * a[n,v]
__global__ void k2_adj(const float* __restrict__ A,
                       const float* __restrict__ w1, const float* __restrict__ b1,
                       const float* __restrict__ w2, const float* __restrict__ b2,
                       const float* __restrict__ w4, const float* __restrict__ b4,
                       const float* __restrict__ sw1, const float* __restrict__ sb1,
                       const float* __restrict__ sw2, const float* __restrict__ sb2) {
    const int n = blockIdx.x;
    const int cblk = blockIdx.y;              // 0..3 -> channels [cblk*16, cblk*16+16)
    const int tid = threadIdx.x;
    const int NT = 256;

    __shared__ float xm_sh[Cc * Vv];      // 1600
    __shared__ float w1s[Rr * Cc], w2s[Rr * Cc], w4s[Cc * Rr];
    __shared__ float sw1s[Hh * Vv], sw2s[Vv * Hh];
    __shared__ float A_s[Vv * Vv];
    __shared__ float b1s[Rr], b2s[Rr], b4s[Cc], sb1s[Hh], sb2s[Vv];
    __shared__ float s_sh[Vv], h_sh[Hh], a_sh[Vv];
    __shared__ float x1_sh[Rr * Vv], x2_sh[Rr * Vv];
    __shared__ float rel_sh[Rr * Vv * Vv]; // 5000

    for (int i = tid; i < Cc * Vv; i += NT) xm_sh[i] = g_xm[n * Cc * Vv + i];
    for (int i = tid; i < Rr * Cc; i += NT) { w1s[i] = w1[i]; w2s[i] = w2[i]; w4s[i] = w4[i]; }
    for (int i = tid; i < Hh * Vv; i += NT) { sw1s[i] = sw1[i]; sw2s[i] = sw2[i]; }
    for (int i = tid; i < Vv * Vv; i += NT) A_s[i] = A[i];
    if (tid < Rr) { b1s[tid] = b1[tid]; b2s[tid] = b2[tid]; }
    if (tid < Cc) b4s[tid] = b4[tid];
    if (tid < Hh) sb1s[tid] = sb1[tid];
    if (tid < Vv) sb2s[tid] = sb2[tid];
    __syncthreads();

    // s[v] = mean over c of xm
    if (tid < Vv) {
        float acc = 0.f;
        for (int c = 0; c < Cc; c++) acc += xm_sh[c * Vv + tid];
        s_sh[tid] = acc * (1.0f / Cc);
    }
    __syncthreads();
    if (tid < Hh) {
        float acc = sb1s[tid];
        for (int v = 0; v < Vv; v++) acc += sw1s[tid * Vv + v] * s_sh[v];
        h_sh[tid] = fmaxf(acc, 0.f);
    }
    __syncthreads();
    if (tid < Vv) {
        float acc = sb2s[tid];
        for (int j = 0; j < Hh; j++) acc += sw2s[tid * Hh + j] * h_sh[j];
        a_sh[tid] = 1.0f / (1.0f + expf(-acc));
    }

    // x1[r,v], x2[r,v]
    for (int i = tid; i < Rr * Vv; i += NT) {
        int r = i / Vv, v = i % Vv;
        float acc1 = b1s[r], acc2 = b2s[r];
        for (int c = 0; c < Cc; c++) {
            float xm = xm_sh[c * Vv + v];
            acc1 += w1s[r * Cc + c] * xm;
            acc2 += w2s[r * Cc + c] * xm;
        }
        x1_sh[i] = acc1;
        x2_sh[i] = acc2;
    }
    __syncthreads();

    // rel[r,u,v] = tanh(x1[r,u] - x2[r,v])
    for (int i = tid; i < Rr * Vv * Vv; i += NT) {
        int r = i / (Vv * Vv), rem = i % (Vv * Vv);
        int u = rem / Vv, v = rem % Vv;
        rel_sh[i] = tanhf(x1_sh[r * Vv + u] - x2_sh[r * Vv + v]);
    }
    __syncthreads();

    // Aeff[c,u,v] for c in this block's 16-channel slice
    const int c0 = cblk * 16;
    float* outp = g_Aeff + ((size_t)n * Cc + c0) * (Vv * Vv);
    for (int i = tid; i < 16 * Vv * Vv; i += NT) {
        int c = c0 + i / (Vv * Vv), rem = i % (Vv * Vv);
        int v = rem % Vv;
        float acc = b4s[c] + A_s[rem];
        #pragma unroll
        for (int r = 0; r < Rr; r++) acc += w4s[c * Rr + r] * rel_sh[r * Vv * Vv + rem];
        outp[i] = acc * a_sh[v];
    }
}

// ============ Kernel 3: out[t,u] = sum_v Aeff[u,v] * x[t,v] per (n,c) ============
// One block per (n,c), 128 threads: one t-row per thread, x row held in 25
// registers. Weights staged in shared as padded 25x28 float rows so a full
// weight row reads as 7 warp-uniform LDS.128 broadcasts. Plain scalar FFMA
// only (no f32x2 — ptxas does not emit packed FFMA2 and the emulation was
// the round-2/3 bottleneck).
__global__ void __launch_bounds__(128) k3_gemm(const float* __restrict__ x,
                                               float* __restrict__ out) {
    __shared__ float xs[Tt * Vv];                      // 12.8 KB; reused as out staging
    __shared__ __align__(16) float Ws[Vv * 28];        // padded rows: 112 B each

    const int b = blockIdx.x;           // n*C + c
    const int tid = threadIdx.x;        // 0..127 == t

    // Load x tile (800 float4, coalesced)
    const float4* xp4 = reinterpret_cast<const float4*>(x + (size_t)b * (Tt * Vv));
    float4* xs4 = reinterpret_cast<float4*>(xs);
    #pragma unroll
    for (int i = tid; i < (Tt * Vv) / 4; i += 128) xs4[i] = xp4[i];

    // Load Aeff row-padded (pad cols 25..27 zeroed so stray lanes stay finite)
    const float* ae = g_Aeff + (size_t)b * (Vv * Vv);
    for (int i = tid; i < Vv * 28; i += 128) {
        int u = i / 28, v = i % 28;
        Ws[i] = (v < Vv) ? ae[u * Vv + v] : 0.f;
    }
    __syncthreads();

    // Pull this thread's x row into registers (lane stride 25 ⊥ 32: conflict-free)
    float xv[Vv];
    #pragma unroll
    for (int v = 0; v < Vv; v++) xv[v] = xs[tid * Vv + v];
    __syncthreads();   // xs now free for output staging

    #pragma unroll 5
    for (int u = 0; u < Vv; u++) {
        const float4* wr = reinterpret_cast<const float4*>(Ws + u * 28);
        float4 w0 = wr[0], w1 = wr[1], w2 = wr[2], w3 = wr[3];
        float4 w4 = wr[4], w5 = wr[5], w6 = wr[6];
        float acc0, acc1;
        acc0  = w0.x * xv[0];
        acc1  = w0.y * xv[1];
        acc0 += w0.z * xv[2];
        acc1 += w0.w * xv[3];
        acc0 += w1.x * xv[4];
        acc1 += w1.y * xv[5];
        acc0 += w1.z * xv[6];
        acc1 += w1.w * xv[7];
        acc0 += w2.x * xv[8];
        acc1 += w2.y * xv[9];
        acc0 += w2.z * xv[10];
        acc1 += w2.w * xv[11];
        acc0 += w3.x * xv[12];
        acc1 += w3.y * xv[13];
        acc0 += w3.z * xv[14];
        acc1 += w3.w * xv[15];
        acc0 += w4.x * xv[16];
        acc1 += w4.y * xv[17];
        acc0 += w4.z * xv[18];
        acc1 += w4.w * xv[19];
        acc0 += w5.x * xv[20];
        acc1 += w5.y * xv[21];
        acc0 += w5.z * xv[22];
        acc1 += w5.w * xv[23];
        acc0 += w6.x * xv[24];
        xs[tid * Vv + u] = acc0 + acc1;
    }
    __syncthreads();

    float4* op4 = reinterpret_cast<float4*>(out + (size_t)b * (Tt * Vv));
    #pragma unroll
    for (int i = tid; i < (Tt * Vv) / 4; i += 128) op4[i] = xs4[i];
}

extern "C" void kernel_launch(void* const* d_in, const int* in_sizes, int n_in,
                              void* d_out, int out_size) {
    const float* x   = (const float*)d_in[0];
    const float* A   = (const float*)d_in[1];
    const float* w1  = (const float*)d_in[2];
    const float* b1  = (const float*)d_in[3];
    const float* w2  = (const float*)d_in[4];
    const float* b2  = (const float*)d_in[5];
    const float* w4  = (const float*)d_in[6];
    const float* b4  = (const float*)d_in[7];
    const float* sw1 = (const float*)d_in[8];
    const float* sb1 = (const float*)d_in[9];
    const float* sw2 = (const float*)d_in[10];
    const float* sb2 = (const float*)d_in[11];
    float* out = (float*)d_out;

    k1_meanT<<<Nn * Cc, 200>>>(x);
    k2_adj<<<dim3(Nn, 4), 256>>>(A, w1, b1, w2, b2, w4, b4, sw1, sb1, sw2, sb2);
    k3_gemm<<<Nn * Cc, 128>>>(x, out);
}

// round 5
// speedup vs baseline: 1.1157x; 1.0379x over previous
#include <cuda_runtime.h>
#include <math.h>

// Problem constants
#define Nn 128
#define Cc 64
#define Tt 128
#define Vv 25
#define Rr 8
#define Hh 12

// Scratch (device global; no allocation allowed)
__device__ float g_Aeff[Nn * Cc * Vv * Vv];   // effective adjacency incl. SE scale (20.5 MB)

// ================= Kernel 12: fused mean_T + SE + relation + Aeff =================
// One block per n, 800 threads (4 channel-groups of 200).
// Phase A: xm[c,v] = mean_t x[n,c,t,v] for all 64 channels (16 iterations of
//          the fixed-v float4 trick: stride 800 float4 == 3200 floats == 0 mod 25).
// Phase B: SE attention a[v], x1/x2, rel=tanh(x1[u]-x2[v]),
//          Aeff[c,u,v] = (sum_r w4[c,r]*rel[r,u,v] + b4[c] + A[u,v]) * a[v]
__global__ void __launch_bounds__(800, 1) k12_stats(
        const float* __restrict__ x,
        const float* __restrict__ A,
        const float* __restrict__ w1, const float* __restrict__ b1,
        const float* __restrict__ w2, const float* __restrict__ b2,
        const float* __restrict__ w4, const float* __restrict__ b4,
        const float* __restrict__ sw1, const float* __restrict__ sb1,
        const float* __restrict__ sw2, const float* __restrict__ sb2) {
    const int n = blockIdx.x;
    const int tid = threadIdx.x;
    const int NT = 800;

    __shared__ float red_rel[Rr * Vv * Vv];   // 5000: phase A 'red' (3200) / phase B 'rel'
    __shared__ float xm_sh[Cc * Vv];          // 1600
    __shared__ float w1s[Rr * Cc], w2s[Rr * Cc], w4s[Cc * Rr];
    __shared__ float sw1s[Hh * Vv], sw2s[Vv * Hh];
    __shared__ float A_s[Vv * Vv];
    __shared__ float b1s[Rr], b2s[Rr], b4s[Cc], sb1s[Hh], sb2s[Vv];
    __shared__ float s_sh[Vv], h_sh[Hh], a_sh[Vv];
    __shared__ float x1_sh[Rr * Vv], x2_sh[Rr * Vv];

    // Stage weights (overlaps with phase A loads)
    for (int i = tid; i < Rr * Cc; i += NT) { w1s[i] = w1[i]; w2s[i] = w2[i]; w4s[i] = w4[i]; }
    for (int i = tid; i < Hh * Vv; i += NT) { sw1s[i] = sw1[i]; sw2s[i] = sw2[i]; }
    for (int i = tid; i < Vv * Vv; i += NT) A_s[i] = A[i];
    if (tid < Rr) { b1s[tid] = b1[tid]; b2s[tid] = b2[tid]; }
    if (tid < Cc) b4s[tid] = b4[tid];
    if (tid < Hh) sb1s[tid] = sb1[tid];
    if (tid < Vv) sb2s[tid] = sb2[tid];

    // ---- Phase A: per-channel mean over T ----
    const int g = tid / 200;          // channel group 0..3
    const int j = tid % 200;          // 0..199
    const float4* x4 = reinterpret_cast<const float4*>(x) + (size_t)n * (Cc * 800);

    for (int it = 0; it < 16; it++) {
        const int c = it * 4 + g;
        const float4* xp4 = x4 + (size_t)c * 800;
        float4 a0 = xp4[j];
        float4 a1 = xp4[j + 200];
        float4 a2 = xp4[j + 400];
        float4 a3 = xp4[j + 600];
        red_rel[g * 800 + 4 * j + 0] = a0.x + a1.x + a2.x + a3.x;
        red_rel[g * 800 + 4 * j + 1] = a0.y + a1.y + a2.y + a3.y;
        red_rel[g * 800 + 4 * j + 2] = a0.z + a1.z + a2.z + a3.z;
        red_rel[g * 800 + 4 * j + 3] = a0.w + a1.w + a2.w + a3.w;
        __syncthreads();
        if (tid < 100) {
            const int gg = tid / Vv, v = tid % Vv;
            float tot = 0.f;
            #pragma unroll
            for (int p = 0; p < 32; p++) tot += red_rel[gg * 800 + v + Vv * p];
            xm_sh[(it * 4 + gg) * Vv + v] = tot * (1.0f / Tt);
        }
        __syncthreads();
    }

    // ---- Phase B ----
    // SE: s[v] = mean_c xm
    if (tid < Vv) {
        float acc = 0.f;
        for (int c = 0; c < Cc; c++) acc += xm_sh[c * Vv + tid];
        s_sh[tid] = acc * (1.0f / Cc);
    }
    __syncthreads();
    if (tid < Hh) {
        float acc = sb1s[tid];
        for (int v = 0; v < Vv; v++) acc += sw1s[tid * Vv + v] * s_sh[v];
        h_sh[tid] = fmaxf(acc, 0.f);
    }
    __syncthreads();
    if (tid < Vv) {
        float acc = sb2s[tid];
        for (int q = 0; q < Hh; q++) acc += sw2s[tid * Hh + q] * h_sh[q];
        a_sh[tid] = 1.0f / (1.0f + expf(-acc));
    }

    // x1[r,v], x2[r,v]
    if (tid < Rr * Vv) {
        int r = tid / Vv, v = tid % Vv;
        float acc1 = b1s[r], acc2 = b2s[r];
        for (int c = 0; c < Cc; c++) {
            float xm = xm_sh[c * Vv + v];
            acc1 += w1s[r * Cc + c] * xm;
            acc2 += w2s[r * Cc + c] * xm;
        }
        x1_sh[tid] = acc1;
        x2_sh[tid] = acc2;
    }
    __syncthreads();

    // rel[r,u,v] = tanh(x1[r,u] - x2[r,v])  (reuses red_rel)
    for (int i = tid; i < Rr * Vv * Vv; i += NT) {
        int r = i / (Vv * Vv), rem = i % (Vv * Vv);
        int u = rem / Vv, v = rem % Vv;
        red_rel[i] = tanhf(x1_sh[r * Vv + u] - x2_sh[r * Vv + v]);
    }
    __syncthreads();

    // Aeff[c,u,v]
    float* outp = g_Aeff + (size_t)n * Cc * Vv * Vv;
    for (int i = tid; i < Cc * Vv * Vv; i += NT) {
        int c = i / (Vv * Vv), rem = i % (Vv * Vv);
        int v = rem % Vv;
        float acc = b4s[c] + A_s[rem];
        #pragma unroll
        for (int r = 0; r < Rr; r++) acc += w4s[c * Rr + r] * red_rel[r * Vv * Vv + rem];
        outp[i] = acc * a_sh[v];
    }
}

// ============ Kernel 3: out[t,u] = sum_v Aeff[u,v] * x[t,v] per (n,c) ============
// One block per (n,c), 128 threads: one t-row per thread, x row held in 25
// registers. Weights staged in shared as padded 25x28 float rows -> 7
// warp-uniform LDS.128 broadcasts per u-row. u-loop kept at unroll 1 to bound
// register pressure (unroll 5 held ~175 weight registers live). Output
// written with streaming stores (never re-read; keep L2 for x).
__global__ void __launch_bounds__(128) k3_gemm(const float* __restrict__ x,
                                               float* __restrict__ out) {
    __shared__ float xs[Tt * Vv];                      // 12.8 KB; reused as out staging
    __shared__ __align__(16) float Ws[Vv * 28];        // padded rows: 112 B each

    const int b = blockIdx.x;           // n*C + c
    const int tid = threadIdx.x;        // 0..127 == t

    // Load x tile (800 float4, coalesced)
    const float4* xp4 = reinterpret_cast<const float4*>(x + (size_t)b * (Tt * Vv));
    float4* xs4 = reinterpret_cast<float4*>(xs);
    #pragma unroll
    for (int i = tid; i < (Tt * Vv) / 4; i += 128) xs4[i] = xp4[i];

    // Load Aeff row-padded (pad cols zeroed)
    const float* ae = g_Aeff + (size_t)b * (Vv * Vv);
    for (int i = tid; i < Vv * 28; i += 128) {
        int u = i / 28, v = i % 28;
        Ws[i] = (v < Vv) ? ae[u * Vv + v] : 0.f;
    }
    __syncthreads();

    // Pull this thread's x row into registers (lane stride 25 ⊥ 32: conflict-free)
    float xv[Vv];
    #pragma unroll
    for (int v = 0; v < Vv; v++) xv[v] = xs[tid * Vv + v];
    __syncthreads();   // xs now free for output staging

    #pragma unroll 1
    for (int u = 0; u < Vv; u++) {
        const float4* wr = reinterpret_cast<const float4*>(Ws + u * 28);
        float4 w0 = wr[0], w1 = wr[1], w2 = wr[2], w3 = wr[3];
        float4 w4 = wr[4], w5 = wr[5], w6 = wr[6];
        float acc0, acc1;
        acc0  = w0.x * xv[0];
        acc1  = w0.y * xv[1];
        acc0 += w0.z * xv[2];
        acc1 += w0.w * xv[3];
        acc0 += w1.x * xv[4];
        acc1 += w1.y * xv[5];
        acc0 += w1.z * xv[6];
        acc1 += w1.w * xv[7];
        acc0 += w2.x * xv[8];
        acc1 += w2.y * xv[9];
        acc0 += w2.z * xv[10];
        acc1 += w2.w * xv[11];
        acc0 += w3.x * xv[12];
        acc1 += w3.y * xv[13];
        acc0 += w3.z * xv[14];
        acc1 += w3.w * xv[15];
        acc0 += w4.x * xv[16];
        acc1 += w4.y * xv[17];
        acc0 += w4.z * xv[18];
        acc1 += w4.w * xv[19];
        acc0 += w5.x * xv[20];
        acc1 += w5.y * xv[21];
        acc0 += w5.z * xv[22];
        acc1 += w5.w * xv[23];
        acc0 += w6.x * xv[24];
        xs[tid * Vv + u] = acc0 + acc1;
    }
    __syncthreads();

    float4* op4 = reinterpret_cast<float4*>(out + (size_t)b * (Tt * Vv));
    #pragma unroll
    for (int i = tid; i < (Tt * Vv) / 4; i += 128) __stcs(op4 + i, xs4[i]);
}

extern "C" void kernel_launch(void* const* d_in, const int* in_sizes, int n_in,
                              void* d_out, int out_size) {
    const float* x   = (const float*)d_in[0];
    const float* A   = (const float*)d_in[1];
    const float* w1  = (const float*)d_in[2];
    const float* b1  = (const float*)d_in[3];
    const float* w2  = (const float*)d_in[4];
    const float* b2  = (const float*)d_in[5];
    const float* w4  = (const float*)d_in[6];
    const float* b4  = (const float*)d_in[7];
    const float* sw1 = (const float*)d_in[8];
    const float* sb1 = (const float*)d_in[9];
    const float* sw2 = (const float*)d_in[10];
    const float* sb2 = (const float*)d_in[11];
    float* out = (float*)d_out;

    k12_stats<<<Nn, 800>>>(x, A, w1, b1, w2, b2, w4, b4, sw1, sb1, sw2, sb2);
    k3_gemm<<<Nn * Cc, 128>>>(x, out);
}